// round 16
// baseline (speedup 1.0000x reference)
#include <cuda_runtime.h>
#include <cstdint>

#define NTOK 262144
#define DF 128
#define CC 64
#define TILES 2048
#define GRID 152
#define NTHR 512

// ---- static device scratch (per-CTA partials) ----
__device__ float g_Fpart[GRID * CC * DF];
__device__ int   g_cntpart[GRID * CC];
__device__ float g_f2part[GRID];
__device__ float g_s2part[CC];
__device__ float g_nc2[CC];

// ---- shared memory byte offsets ----
#define SM_A0    0          // float[128*132] raw f32 tile buf 0 (67584)
#define SM_A1    67584      // float[128*132] raw f32 tile buf 1; ctf alias at init
#define SM_FSUM  135168     // float[64*132]  per-CTA class sums (33792)
#define SM_F2    168960     // float[128]
#define SM_C2    169472     // float[64]
#define SM_LBL   169728     // int[128]
#define SM_CNT   170240     // int[64]
#define SM_CNTT  170496     // int[64]
#define SM_LIST  170752     // u8[64*128] (8192)
#define SM_TOTAL 178944

__device__ __forceinline__ uint32_t smem_u32(const void* p) {
    uint32_t a;
    asm("{ .reg .u64 t; cvta.to.shared.u64 t, %1; cvt.u32.u64 %0, t; }" : "=r"(a) : "l"(p));
    return a;
}
__device__ __forceinline__ float tf32r(float x) {
    unsigned u;
    asm("cvt.rna.tf32.f32 %0, %1;" : "=r"(u) : "f"(x));
    return __uint_as_float(u);
}
__device__ __forceinline__ void mma_tf32(float* d, float a0, float a1,
                                         float a2, float a3,
                                         unsigned b0, unsigned b1) {
    asm volatile(
        "mma.sync.aligned.m16n8k8.row.col.f32.tf32.tf32.f32 "
        "{%0,%1,%2,%3}, {%4,%5,%6,%7}, {%8,%9}, {%0,%1,%2,%3};"
        : "+f"(d[0]), "+f"(d[1]), "+f"(d[2]), "+f"(d[3])
        : "r"(__float_as_uint(a0)), "r"(__float_as_uint(a1)),
          "r"(__float_as_uint(a2)), "r"(__float_as_uint(a3)),
          "r"(b0), "r"(b1));
}
#define CP16(dst, src)  asm volatile("cp.async.cg.shared.global [%0], [%1], 16;" :: "r"(dst), "l"(src))
#define CP_COMMIT()     asm volatile("cp.async.commit_group;" ::: "memory")
#define CP_WAIT1()      asm volatile("cp.async.wait_group 1;" ::: "memory")
#define CP_WAIT0()      asm volatile("cp.async.wait_group 0;" ::: "memory")

// ============================================================
__global__ void __launch_bounds__(NTHR, 1)
k_main(const float* __restrict__ feature, const int* __restrict__ label,
       const float* __restrict__ centers, float* __restrict__ out)
{
    extern __shared__ __align__(16) char sm[];
    float*         F_sm    = (float*)(sm + SM_FSUM);
    float*         ctf     = (float*)(sm + SM_A1);      // init-time alias
    float*         f2_sm   = (float*)(sm + SM_F2);
    float*         c2_sm   = (float*)(sm + SM_C2);
    int*           lbl_sm  = (int*)(sm + SM_LBL);
    int*           cnt_sm  = (int*)(sm + SM_CNT);
    int*           cntt_sm = (int*)(sm + SM_CNTT);
    unsigned char* list_sm = (unsigned char*)(sm + SM_LIST);

    const int tid = threadIdx.x, bid = blockIdx.x;
    const int w = tid >> 5, l = tid & 31;
    const int lq = l >> 2, lr = l & 3;
    const int mbase = (w >> 2) * 32;            // 4 m-groups of 32 tokens
    const int nbase = (w & 3) * 16;             // 4 n-groups of 16 classes
    const uint32_t smb = smem_u32(sm);

    // ---- prologue: stream tile `bid` into buf 0 ----
    {
        const char* src = (const char*)(feature + (size_t)bid * 128 * DF);
        #pragma unroll
        for (int it = 0; it < 8; it++) {
            const int c = it * NTHR + tid;      // 16B chunk id 0..4095
            const int row = c >> 5, off = (c & 31) * 16;
            CP16(smb + SM_A0 + row * 528 + off, src + row * 512 + off);
        }
        CP_COMMIT();
    }

    // ---- one-time init (ctf staged in buf 1, consumed into regs pre-loop) ----
    for (int i = tid; i < CC * 132; i += NTHR) F_sm[i] = 0.f;
    for (int i = tid; i < CC * DF; i += NTHR) {
        int n = i >> 7, k = i & 127;
        ctf[n * 132 + k] = tf32r(centers[i]);
    }
    if (tid < CC) {
        float s = 0.f;
        for (int k = 0; k < DF; k++) { float c = centers[tid * DF + k]; s += c * c; }
        c2_sm[tid] = s;
        cntt_sm[tid] = 0;
    }
    __syncthreads();

    // ---- persistent B fragments: classes nbase..nbase+15, all K ----
    unsigned bfr[16][2][2];
    #pragma unroll
    for (int kc = 0; kc < 16; kc++)
        #pragma unroll
        for (int j = 0; j < 2; j++) {
            const float* cp = &ctf[(nbase + j * 8 + lq) * 132 + kc * 8 + lr];
            bfr[kc][j][0] = __float_as_uint(cp[0]);
            bfr[kc][j][1] = __float_as_uint(cp[4]);
        }
    __syncthreads();                             // ctf consumed; buf 1 free

    double f2acc = 0.0;
    int par = 0;

    for (int tile = bid; tile < TILES; tile += GRID) {
        __syncthreads();                         // S1: prev phase-3 on ¬cur done
        const int base = tile * 128;
        const float* atf = (const float*)(sm + (par ? SM_A1 : SM_A0));

        // ---- prefetch next tile into the other buffer ----
        const int nxt = tile + GRID;
        if (nxt < TILES) {
            const char* src = (const char*)(feature + (size_t)nxt * 128 * DF);
            const uint32_t dst = smb + (par ? SM_A0 : SM_A1);
            #pragma unroll
            for (int it = 0; it < 8; it++) {
                const int c = it * NTHR + tid;
                const int row = c >> 5, off = (c & 31) * 16;
                CP16(dst + row * 528 + off, src + row * 512 + off);
            }
            CP_COMMIT();
            CP_WAIT1();                          // current tile's group complete
        } else {
            CP_WAIT0();
        }

        if (tid < 128)      lbl_sm[tid] = label[base + tid] & (CC - 1);
        else if (tid < 192) cnt_sm[tid - 128] = 0;
        __syncthreads();                         // S2: tile + labels visible

        // ---- per-tile class row lists ----
        if (tid < 128) {
            int c = lbl_sm[tid];
            int pos = atomicAdd(&cnt_sm[c], 1);
            list_sm[c * 128 + pos] = (unsigned char)tid;
        }

        // ---- GEMM (tf32 cvt in-register) + exact f2 from raw values ----
        float acc[2][2][4];
        float u[2][2];
        #pragma unroll
        for (int mi = 0; mi < 2; mi++) {
            u[mi][0] = 0.f; u[mi][1] = 0.f;
            #pragma unroll
            for (int j = 0; j < 2; j++)
                #pragma unroll
                for (int e = 0; e < 4; e++) acc[mi][j][e] = 0.f;
        }

        #pragma unroll
        for (int kc = 0; kc < 16; kc++) {
            #pragma unroll
            for (int mi = 0; mi < 2; mi++) {
                const float* ap = &atf[(mbase + mi * 16 + lq) * 132 + kc * 8 + lr];
                const float r0 = ap[0];
                const float r2 = ap[4];
                const float r1 = ap[8 * 132];
                const float r3 = ap[8 * 132 + 4];
                u[mi][0] = fmaf(r0, r0, u[mi][0]);
                u[mi][0] = fmaf(r2, r2, u[mi][0]);
                u[mi][1] = fmaf(r1, r1, u[mi][1]);
                u[mi][1] = fmaf(r3, r3, u[mi][1]);
                const float fa0 = tf32r(r0), fa1 = tf32r(r1);
                const float fa2 = tf32r(r2), fa3 = tf32r(r3);
                mma_tf32(acc[mi][0], fa0, fa1, fa2, fa3, bfr[kc][0][0], bfr[kc][0][1]);
                mma_tf32(acc[mi][1], fa0, fa1, fa2, fa3, bfr[kc][1][0], bfr[kc][1][1]);
            }
        }
        // quad-reduce f2 across lr lanes
        #pragma unroll
        for (int mi = 0; mi < 2; mi++)
            #pragma unroll
            for (int j = 0; j < 2; j++) {
                u[mi][j] += __shfl_xor_sync(0xffffffffu, u[mi][j], 1);
                u[mi][j] += __shfl_xor_sync(0xffffffffu, u[mi][j], 2);
            }
        // n0 warps publish f2 for the loss accumulator
        if ((w & 3) == 0 && lr == 0) {
            #pragma unroll
            for (int mi = 0; mi < 2; mi++) {
                f2_sm[mbase + mi * 16 + lq]     = u[mi][0];
                f2_sm[mbase + mi * 16 + lq + 8] = u[mi][1];
            }
        }

        // ---- epilogue: dist = f2 + c2 - 2*dot, direct scalar STG ----
        {
            float* gdst = out + 1 + CC * DF + (size_t)tile * 8192;
            #pragma unroll
            for (int mi = 0; mi < 2; mi++) {
                const int r0 = mbase + mi * 16 + lq;
                const float ft0 = u[mi][0], ft1 = u[mi][1];
                #pragma unroll
                for (int j = 0; j < 2; j++) {
                    const int n0 = nbase + j * 8 + lr * 2;
                    const float cA = c2_sm[n0], cB = c2_sm[n0 + 1];
                    gdst[r0 * CC + n0]           = fmaf(-2.f, acc[mi][j][0], ft0 + cA);
                    gdst[r0 * CC + n0 + 1]       = fmaf(-2.f, acc[mi][j][1], ft0 + cB);
                    gdst[(r0 + 8) * CC + n0]     = fmaf(-2.f, acc[mi][j][2], ft1 + cA);
                    gdst[(r0 + 8) * CC + n0 + 1] = fmaf(-2.f, acc[mi][j][3], ft1 + cB);
                }
            }
        }
        __syncthreads();                         // S3: lists + f2_sm complete

        // ---- phase 3: warp owns 4 classes; raw f32 rows ----
        {
            #pragma unroll
            for (int cc = 0; cc < 4; cc++) {
                const int c = w * 4 + cc;
                const int n = cnt_sm[c];
                if (n) {
                    const unsigned char* lst = list_sm + c * 128;
                    float4 a = make_float4(0.f, 0.f, 0.f, 0.f);
                    for (int i = 0; i < n; i++) {
                        const int r = lst[i];                    // broadcast LDS
                        const float4 v = *(const float4*)&atf[r * 132 + l * 4];
                        a.x += v.x; a.y += v.y; a.z += v.z; a.w += v.w;
                    }
                    float4* Fp = (float4*)&F_sm[c * 132 + l * 4];
                    float4 f = *Fp;
                    f.x += a.x; f.y += a.y; f.z += a.z; f.w += a.w;
                    *Fp = f;
                }
            }
        }
        if (tid < CC)  cntt_sm[tid] += cnt_sm[tid];
        if (tid < 128) f2acc += (double)f2_sm[tid];
        par ^= 1;
    }

    // ---- flush per-CTA partials (deterministic slots) ----
    __syncthreads();
    for (int i = tid; i < CC * DF; i += NTHR)
        g_Fpart[bid * CC * DF + i] = F_sm[(i >> 7) * 132 + (i & 127)];
    if (tid < CC) g_cntpart[bid * CC + tid] = cntt_sm[tid];
    {
        double* dred = (double*)(sm + SM_A0);    // buf 0 free now
        dred[tid] = (tid < 128) ? f2acc : 0.0;
        __syncthreads();
        if (tid == 0) {
            double s0 = 0, s1 = 0, s2 = 0, s3 = 0;
            for (int i = 0; i < 128; i += 4) {
                s0 += dred[i]; s1 += dred[i + 1]; s2 += dred[i + 2]; s3 += dred[i + 3];
            }
            g_f2part[bid] = (float)((s0 + s1) + (s2 + s3));
        }
    }
}

// ============================================================
// finalize 1: one block per class (64 x 128 threads)
// ============================================================
__global__ void __launch_bounds__(128)
k_final1(const float* __restrict__ centers, float* __restrict__ out)
{
    __shared__ float red[128];
    __shared__ int   ired[128];
    __shared__ int   ncls;
    const int c = blockIdx.x, t = threadIdx.x;

    int s = (t < GRID) ? g_cntpart[t * CC + c] : 0;
    if (t + 128 < GRID) s += g_cntpart[(t + 128) * CC + c];
    ired[t] = s;
    __syncthreads();
    for (int off = 64; off; off >>= 1) {
        if (t < off) ired[t] += ired[t + off];
        __syncthreads();
    }
    if (t == 0) ncls = ired[0];
    __syncthreads();
    const int n = ncls;

    const int i = c * DF + t;
    float F0 = 0, F1 = 0, F2 = 0, F3 = 0, F4 = 0, F5 = 0, F6 = 0, F7 = 0;
    #pragma unroll 4
    for (int b = 0; b < GRID; b += 8) {
        F0 += g_Fpart[(b + 0) * CC * DF + i];
        F1 += g_Fpart[(b + 1) * CC * DF + i];
        F2 += g_Fpart[(b + 2) * CC * DF + i];
        F3 += g_Fpart[(b + 3) * CC * DF + i];
        F4 += g_Fpart[(b + 4) * CC * DF + i];
        F5 += g_Fpart[(b + 5) * CC * DF + i];
        F6 += g_Fpart[(b + 6) * CC * DF + i];
        F7 += g_Fpart[(b + 7) * CC * DF + i];
    }
    const float F = ((F0 + F1) + (F2 + F3)) + ((F4 + F5) + (F6 + F7));
    const float cen = centers[i];
    out[1 + i] = (n > 0) ? (cen - F / (float)n) : 0.f;

    red[t] = F * cen;
    __syncthreads();
    for (int off = 64; off; off >>= 1) {
        if (t < off) red[t] += red[t + off];
        __syncthreads();
    }
    if (t == 0) g_s2part[c] = red[0];
    __syncthreads();
    red[t] = cen * cen;
    __syncthreads();
    for (int off = 64; off; off >>= 1) {
        if (t < off) red[t] += red[t + off];
        __syncthreads();
    }
    if (t == 0) g_nc2[c] = (float)n * red[0];
}

// ============================================================
// finalize 2: micro kernel for the loss scalar
// ============================================================
__global__ void __launch_bounds__(128)
k_final2(float* __restrict__ out)
{
    __shared__ float r1[128], r2[128], r3[128];
    const int t = threadIdx.x;
    float a = (t < GRID) ? g_f2part[t] : 0.f;
    if (t + 128 < GRID) a += g_f2part[t + 128];
    r1[t] = a;
    r2[t] = (t < CC) ? g_s2part[t] : 0.f;
    r3[t] = (t < CC) ? g_nc2[t] : 0.f;
    __syncthreads();
    for (int off = 64; off; off >>= 1) {
        if (t < off) { r1[t] += r1[t + off]; r2[t] += r2[t + off]; r3[t] += r3[t + off]; }
        __syncthreads();
    }
    if (t == 0)
        out[0] = (float)(((double)r1[0] - 2.0 * (double)r2[0] + (double)r3[0])
                         / ((double)NTOK * (double)DF));
}

// ============================================================
extern "C" void kernel_launch(void* const* d_in, const int* in_sizes, int n_in,
                              void* d_out, int out_size)
{
    const float* feature = (const float*)d_in[0];
    const int*   label   = (const int*)d_in[1];
    const float* centers = (const float*)d_in[2];
    float*       out     = (float*)d_out;

    cudaFuncSetAttribute(k_main, cudaFuncAttributeMaxDynamicSharedMemorySize, SM_TOTAL);
    k_main<<<GRID, NTHR, SM_TOTAL>>>(feature, label, centers, out);
    k_final1<<<CC, 128>>>(centers, out);
    k_final2<<<1, 128>>>(out);
}

// round 17
// speedup vs baseline: 1.0546x; 1.0546x over previous
#include <cuda_runtime.h>
#include <cstdint>

#define NTOK 262144
#define DF 128
#define CC 64
#define TILES 2048
#define GRID 152
#define NTHR 512

// ---- static device scratch (per-CTA partials) ----
__device__ float g_Fpart[GRID * CC * DF];
__device__ int   g_cntpart[GRID * CC];
__device__ float g_f2part[GRID];
__device__ float g_s2part[CC];
__device__ float g_nc2[CC];

// ---- shared memory byte offsets ----
#define SM_ATF   0          // float[128*132] tf32-rounded feature tile
#define SM_CTF   67584      // float[64*132]  tf32-rounded centers
#define SM_FSUM  101376     // float[64*132]  per-CTA class sums
#define SM_DRED  135168     // double[512] final f2 reduce (ctf alias until end)
#define SM_F2    169472     // float[128]
#define SM_C2    169984     // float[64]
#define SM_LBL   170240     // int[128]
#define SM_CNT   170752     // int[64]
#define SM_CNTT  171008     // int[64]
#define SM_LIST  171264     // u8[64*128]
#define SM_TOTAL 179456

__device__ __forceinline__ float tf32r(float x) {
    unsigned u;
    asm("cvt.rna.tf32.f32 %0, %1;" : "=r"(u) : "f"(x));
    return __uint_as_float(u);
}
__device__ __forceinline__ void mma_tf32(float* d, float a0, float a1,
                                         float a2, float a3,
                                         unsigned b0, unsigned b1) {
    asm volatile(
        "mma.sync.aligned.m16n8k8.row.col.f32.tf32.tf32.f32 "
        "{%0,%1,%2,%3}, {%4,%5,%6,%7}, {%8,%9}, {%0,%1,%2,%3};"
        : "+f"(d[0]), "+f"(d[1]), "+f"(d[2]), "+f"(d[3])
        : "r"(__float_as_uint(a0)), "r"(__float_as_uint(a1)),
          "r"(__float_as_uint(a2)), "r"(__float_as_uint(a3)),
          "r"(b0), "r"(b1));
}

// ============================================================
__global__ void __launch_bounds__(NTHR, 1)
k_main(const float* __restrict__ feature, const int* __restrict__ label,
       const float* __restrict__ centers, float* __restrict__ out)
{
    extern __shared__ __align__(16) char sm[];
    float*         atf     = (float*)(sm + SM_ATF);
    float*         ctf     = (float*)(sm + SM_CTF);
    float*         F_sm    = (float*)(sm + SM_FSUM);
    float*         f2_sm   = (float*)(sm + SM_F2);
    float*         c2_sm   = (float*)(sm + SM_C2);
    int*           lbl_sm  = (int*)(sm + SM_LBL);
    int*           cnt_sm  = (int*)(sm + SM_CNT);
    int*           cntt_sm = (int*)(sm + SM_CNTT);
    unsigned char* list_sm = (unsigned char*)(sm + SM_LIST);

    const int tid = threadIdx.x, bid = blockIdx.x;
    const int w = tid >> 5, l = tid & 31;
    const int lq = l >> 2, lr = l & 3;
    const int mbase = (w >> 2) * 32;            // 4 m-groups of 32 tokens
    const int nbase = (w & 3) * 16;             // 4 n-groups of 16 classes

    // ---- one-time init ----
    for (int i = tid; i < CC * 132; i += NTHR) F_sm[i] = 0.f;
    for (int i = tid; i < CC * DF; i += NTHR) {
        int n = i >> 7, k = i & 127;
        ctf[n * 132 + k] = tf32r(centers[i]);
    }
    if (tid < CC) {
        float s = 0.f;
        for (int k = 0; k < DF; k++) { float c = centers[tid * DF + k]; s += c * c; }
        c2_sm[tid] = s;
        cntt_sm[tid] = 0;
    }
    __syncthreads();

    // ---- persistent B fragments: classes nbase..nbase+15, all K ----
    unsigned bfr[16][2][2];
    #pragma unroll
    for (int kc = 0; kc < 16; kc++)
        #pragma unroll
        for (int j = 0; j < 2; j++) {
            const float* cp = &ctf[(nbase + j * 8 + lq) * 132 + kc * 8 + lr];
            bfr[kc][j][0] = __float_as_uint(cp[0]);
            bfr[kc][j][1] = __float_as_uint(cp[4]);
        }

    double f2acc = 0.0;

    for (int tile = bid; tile < TILES; tile += GRID) {
        __syncthreads();                         // S1: atf reuse safe (prev phase3 done)
        const int base = tile * 128;

        if (tid < 128)      lbl_sm[tid] = label[base + tid] & (CC - 1);
        else if (tid < 192) cnt_sm[tid - 128] = 0;

        // ---- load, tf32-round, store tile (no shfl chains) ----
        #pragma unroll
        for (int it = 0; it < 8; it++) {
            const int v = it * NTHR + tid;
            const int tok = v >> 5, i4 = v & 31;    // warp = one token row
            float4 f4 = *(const float4*)&feature[(size_t)(base + tok) * DF + i4 * 4];
            f4.x = tf32r(f4.x); f4.y = tf32r(f4.y);
            f4.z = tf32r(f4.z); f4.w = tf32r(f4.w);
            *(float4*)&atf[tok * 132 + i4 * 4] = f4;
        }
        __syncthreads();                         // S2: tile + labels visible

        // ---- per-tile class row lists ----
        if (tid < 128) {
            int c = lbl_sm[tid];
            int pos = atomicAdd(&cnt_sm[c], 1);
            list_sm[c * 128 + pos] = (unsigned char)tid;
        }

        // ---- GEMM + in-register f2: 32 tokens x 16 classes per warp ----
        float acc[2][2][4];
        float u[2][2];
        #pragma unroll
        for (int mi = 0; mi < 2; mi++) {
            u[mi][0] = 0.f; u[mi][1] = 0.f;
            #pragma unroll
            for (int j = 0; j < 2; j++)
                #pragma unroll
                for (int e = 0; e < 4; e++) acc[mi][j][e] = 0.f;
        }

        #pragma unroll
        for (int kc = 0; kc < 16; kc++) {
            #pragma unroll
            for (int mi = 0; mi < 2; mi++) {
                const float* ap = &atf[(mbase + mi * 16 + lq) * 132 + kc * 8 + lr];
                const float fa0 = ap[0];
                const float fa2 = ap[4];
                const float fa1 = ap[8 * 132];
                const float fa3 = ap[8 * 132 + 4];
                u[mi][0] = fmaf(fa0, fa0, u[mi][0]);
                u[mi][0] = fmaf(fa2, fa2, u[mi][0]);
                u[mi][1] = fmaf(fa1, fa1, u[mi][1]);
                u[mi][1] = fmaf(fa3, fa3, u[mi][1]);
                mma_tf32(acc[mi][0], fa0, fa1, fa2, fa3, bfr[kc][0][0], bfr[kc][0][1]);
                mma_tf32(acc[mi][1], fa0, fa1, fa2, fa3, bfr[kc][1][0], bfr[kc][1][1]);
            }
        }
        // quad-reduce f2 across lr lanes (bits 0-1 of lane id)
        #pragma unroll
        for (int mi = 0; mi < 2; mi++)
            #pragma unroll
            for (int j = 0; j < 2; j++) {
                u[mi][j] += __shfl_xor_sync(0xffffffffu, u[mi][j], 1);
                u[mi][j] += __shfl_xor_sync(0xffffffffu, u[mi][j], 2);
            }
        // n0 warps publish f2 for the loss accumulator
        if ((w & 3) == 0 && lr == 0) {
            #pragma unroll
            for (int mi = 0; mi < 2; mi++) {
                f2_sm[mbase + mi * 16 + lq]     = u[mi][0];
                f2_sm[mbase + mi * 16 + lq + 8] = u[mi][1];
            }
        }

        // ---- epilogue: dist = f2 + c2 - 2*dot, direct scalar STG ----
        {
            float* gdst = out + 1 + CC * DF + (size_t)tile * 8192;
            #pragma unroll
            for (int mi = 0; mi < 2; mi++) {
                const int r0 = mbase + mi * 16 + lq;
                const float ft0 = u[mi][0], ft1 = u[mi][1];
                #pragma unroll
                for (int j = 0; j < 2; j++) {
                    const int n0 = nbase + j * 8 + lr * 2;
                    const float cA = c2_sm[n0], cB = c2_sm[n0 + 1];
                    gdst[r0 * CC + n0]           = fmaf(-2.f, acc[mi][j][0], ft0 + cA);
                    gdst[r0 * CC + n0 + 1]       = fmaf(-2.f, acc[mi][j][1], ft0 + cB);
                    gdst[(r0 + 8) * CC + n0]     = fmaf(-2.f, acc[mi][j][2], ft1 + cA);
                    gdst[(r0 + 8) * CC + n0 + 1] = fmaf(-2.f, acc[mi][j][3], ft1 + cB);
                }
            }
        }
        __syncthreads();                         // S3: lists + f2_sm complete

        // ---- phase 3: warp owns 4 classes; whole class row in registers ----
        {
            #pragma unroll
            for (int cc = 0; cc < 4; cc++) {
                const int c = w * 4 + cc;
                const int n = cnt_sm[c];
                if (n) {
                    const unsigned char* lst = list_sm + c * 128;
                    float4 a = make_float4(0.f, 0.f, 0.f, 0.f);
                    for (int i = 0; i < n; i++) {
                        const int r = lst[i];                    // broadcast LDS
                        const float4 v = *(const float4*)&atf[r * 132 + l * 4];
                        a.x += v.x; a.y += v.y; a.z += v.z; a.w += v.w;
                    }
                    float4* Fp = (float4*)&F_sm[c * 132 + l * 4];
                    float4 f = *Fp;
                    f.x += a.x; f.y += a.y; f.z += a.z; f.w += a.w;
                    *Fp = f;
                }
            }
        }
        if (tid < CC)  cntt_sm[tid] += cnt_sm[tid];
        if (tid < 128) f2acc += (double)f2_sm[tid];
    }

    // ---- flush per-CTA partials (deterministic slots) ----
    __syncthreads();
    for (int i = tid; i < CC * DF; i += NTHR)
        g_Fpart[bid * CC * DF + i] = F_sm[(i >> 7) * 132 + (i & 127)];
    if (tid < CC) g_cntpart[bid * CC + tid] = cntt_sm[tid];
    {
        double* dred = (double*)(sm + SM_DRED);
        dred[tid] = (tid < 128) ? f2acc : 0.0;
        __syncthreads();
        if (tid == 0) {
            double s0 = 0, s1 = 0, s2 = 0, s3 = 0;
            for (int i = 0; i < 128; i += 4) {
                s0 += dred[i]; s1 += dred[i + 1]; s2 += dred[i + 2]; s3 += dred[i + 3];
            }
            g_f2part[bid] = (float)((s0 + s1) + (s2 + s3));
        }
    }
}

// ============================================================
// finalize 1: one block per class, 256 threads (partials split in half)
// ============================================================
__global__ void __launch_bounds__(256)
k_final1(const float* __restrict__ centers, float* __restrict__ out)
{
    __shared__ float Fh[256];
    __shared__ float r2[256], r3[256];
    __shared__ int   ired[256];
    __shared__ int   ncls;
    const int c = blockIdx.x, t = threadIdx.x;

    // n_c over 152 partials
    ired[t] = (t < GRID) ? g_cntpart[t * CC + c] : 0;
    __syncthreads();
    for (int off = 128; off; off >>= 1) {
        if (t < off) ired[t] += ired[t + off];
        __syncthreads();
    }
    if (t == 0) ncls = ired[0];
    __syncthreads();
    const int n = ncls;

    // F[c][d] over 152 partials: two half-chains of 76 (ILP-4) per d
    const int d  = t & 127;
    const int b0 = (t < 128) ? 0 : 76;
    const int i  = c * DF + d;
    {
        float F0 = 0.f, F1 = 0.f, F2 = 0.f, F3 = 0.f;
        #pragma unroll 4
        for (int b = b0; b < b0 + 76; b += 4) {
            F0 += g_Fpart[(b + 0) * CC * DF + i];
            F1 += g_Fpart[(b + 1) * CC * DF + i];
            F2 += g_Fpart[(b + 2) * CC * DF + i];
            F3 += g_Fpart[(b + 3) * CC * DF + i];
        }
        Fh[t] = (F0 + F1) + (F2 + F3);
    }
    __syncthreads();

    if (t < 128) {
        const float F   = Fh[t] + Fh[t + 128];
        const float cen = centers[i];
        out[1 + i] = (n > 0) ? (cen - F / (float)n) : 0.f;
        r2[t] = F * cen;
        r3[t] = cen * cen;
    } else {
        r2[t] = 0.f;
        r3[t] = 0.f;
    }
    __syncthreads();
    for (int off = 128; off; off >>= 1) {
        if (t < off) { r2[t] += r2[t + off]; r3[t] += r3[t + off]; }
        __syncthreads();
    }
    if (t == 0) {
        g_s2part[c] = r2[0];
        g_nc2[c]    = (float)n * r3[0];
    }
}

// ============================================================
// finalize 2: micro kernel for the loss scalar
// ============================================================
__global__ void __launch_bounds__(128)
k_final2(float* __restrict__ out)
{
    __shared__ float r1[128], r2[128], r3[128];
    const int t = threadIdx.x;
    float a = (t < GRID) ? g_f2part[t] : 0.f;
    if (t + 128 < GRID) a += g_f2part[t + 128];
    r1[t] = a;
    r2[t] = (t < CC) ? g_s2part[t] : 0.f;
    r3[t] = (t < CC) ? g_nc2[t] : 0.f;
    __syncthreads();
    for (int off = 64; off; off >>= 1) {
        if (t < off) { r1[t] += r1[t + off]; r2[t] += r2[t + off]; r3[t] += r3[t + off]; }
        __syncthreads();
    }
    if (t == 0)
        out[0] = (float)(((double)r1[0] - 2.0 * (double)r2[0] + (double)r3[0])
                         / ((double)NTOK * (double)DF));
}

// ============================================================
extern "C" void kernel_launch(void* const* d_in, const int* in_sizes, int n_in,
                              void* d_out, int out_size)
{
    const float* feature = (const float*)d_in[0];
    const int*   label   = (const int*)d_in[1];
    const float* centers = (const float*)d_in[2];
    float*       out     = (float*)d_out;

    cudaFuncSetAttribute(k_main, cudaFuncAttributeMaxDynamicSharedMemorySize, SM_TOTAL);
    k_main<<<GRID, NTHR, SM_TOTAL>>>(feature, label, centers, out);
    k_final1<<<CC, 256>>>(centers, out);
    k_final2<<<1, 128>>>(out);
}